// round 13
// baseline (speedup 1.0000x reference)
#include <cuda_runtime.h>
#include <cstdint>

#define NB 32
#define NC 256
#define NHW 3136
#define NHW4 784
#define NG 32
#define EPSV 1e-5f

#define GRID_BLOCKS 740      // 5 * 148, co-resident at 5 blocks/SM
#define TPB 256
#define NSTAGE 4
#define PLANES_PER_STAGE 2048
#define BATCHES_PER_STAGE 8
#define PLANE_BYTES (NHW * 4)   // 12544
#define NBUF 3

__device__ float4 d_coef[NC];          // (gs, gsh, ms, msh) per channel
__device__ float  d_dot[NB];           // alpha dot accumulators (zero-init)

__device__ unsigned int bar_count = 0;
__device__ volatile unsigned int bar_gen = 0;
__device__ unsigned int pool_ctr[NSTAGE];
__device__ unsigned int apply_ctr[NSTAGE];

__device__ __forceinline__ void grid_barrier_reset(int s) {
    __threadfence();          // publish pool-phase writes (dots via atomics)
    __syncthreads();
    if (threadIdx.x == 0) {
        const unsigned int gen = bar_gen;
        if (atomicAdd(&bar_count, 1u) == GRID_BLOCKS - 1) {
            bar_count    = 0;
            pool_ctr[s]  = 0;                 // fully consumed this phase
            apply_ctr[s] = 0;                 // consumed last replay
            // reset next stage's dots: accumulated only after this barrier,
            // consumed (this replay) after barrier(s+1); prior replay sealed
            // by the kernel boundary.
            const int ob = ((s + 1) % NSTAGE) * BATCHES_PER_STAGE;
            #pragma unroll
            for (int i = 0; i < BATCHES_PER_STAGE; i++) d_dot[ob + i] = 0.0f;
            __threadfence();
            bar_gen = gen + 1;                // release
        } else {
            while (bar_gen == gen) __nanosleep(32);
        }
        __threadfence();                      // acquire
    }
    __syncthreads();
}

__global__ __launch_bounds__(TPB, 5)
void fused_kernel(const float* __restrict__ x, float* __restrict__ out,
                  const float* __restrict__ alpha_w,
                  const float* __restrict__ alpha_b,
                  const float* __restrict__ g_w,
                  const float* __restrict__ g_b,
                  const float* __restrict__ g_rm,
                  const float* __restrict__ g_rv,
                  const float* __restrict__ grp_w,
                  const float* __restrict__ grp_b,
                  const float* __restrict__ grp_rm,
                  const float* __restrict__ grp_rv) {
    __shared__ __align__(128) float sbuf[NBUF][NHW];   // 3 x 12.25KB
    __shared__ unsigned int s_grain;

    const int tid  = threadIdx.x;
    const int lane = tid & 31;

    // block 0 builds the per-channel coefficient table while others pool
    if (blockIdx.x == 0) {
        const int c = tid;
        const float gs  = g_w[c] * rsqrtf(g_rv[c] + EPSV);
        const float gsh = g_b[c] - g_rm[c] * gs;
        float ms = 0.0f, msh = 0.0f;
        #pragma unroll 8
        for (int g = 0; g < NG; g++) {
            const int idx = g * NC + c;
            const float sg = grp_w[idx] * rsqrtf(grp_rv[idx] + EPSV);
            ms  += sg;
            msh += grp_b[idx] - grp_rm[idx] * sg;
        }
        d_coef[c] = make_float4(gs, gsh, ms * (1.0f / (float)NG),
                                         msh * (1.0f / (float)NG));
    }

    int buf = 0;   // TMA buffer cursor persists across stages

    #pragma unroll 1
    for (int stage = 0; stage < NSTAGE; stage++) {

        // ---------- pool phase: warp-steal whole planes, fold alpha-dot ----
        for (;;) {
            unsigned int pz;
            if (lane == 0) pz = atomicAdd(&pool_ctr[stage], 1u);
            pz = __shfl_sync(0xffffffffu, pz, 0);
            if (pz >= PLANES_PER_STAGE) break;
            const int plane = stage * PLANES_PER_STAGE + (int)pz;

            const float4* __restrict__ xp =
                reinterpret_cast<const float4*>(x) + (size_t)plane * NHW4;
            float s = 0.0f;
            float4 v[6];
            #pragma unroll
            for (int b = 0; b < 4; b++) {            // 4*6*32 = 768
                #pragma unroll
                for (int k = 0; k < 6; k++)
                    v[k] = xp[lane + (b * 6 + k) * 32];
                #pragma unroll
                for (int k = 0; k < 6; k++)
                    s += (v[k].x + v[k].y) + (v[k].z + v[k].w);
            }
            if (lane < 16) {                         // tail 16
                float4 t = xp[768 + lane];
                s += (t.x + t.y) + (t.z + t.w);
            }
            #pragma unroll
            for (int o = 16; o > 0; o >>= 1)
                s += __shfl_down_sync(0xffffffffu, s, o);
            if (lane == 0) {
                const float p = s * (1.0f / (float)NHW);
                atomicAdd(&d_dot[plane >> 8], p * alpha_w[plane & 255]);
            }
        }

        grid_barrier_reset(stage);

        // ---------- apply phase: block-steal planes; 3-deep TMA pipeline ---
        for (;;) {
            if (tid == 0) s_grain = atomicAdd(&apply_ctr[stage], 1u);
            __syncthreads();
            const unsigned int g = s_grain;
            if (g >= PLANES_PER_STAGE) break;
            const int plane = stage * PLANES_PER_STAGE + (int)g;

            const float4 cf = d_coef[plane & 255];
            const float a   = 1.0f / (1.0f + expf(-(d_dot[plane >> 8] + alpha_b[0])));
            const float na  = 1.0f - a;
            const float sc  = na * cf.x + a * cf.z;
            const float sf  = na * cf.y + a * cf.w;

            // allow 2 stores in flight; ensure this buffer's old store drained
            if (tid == 0)
                asm volatile("cp.async.bulk.wait_group 2;" ::: "memory");
            __syncthreads();

            const float4* __restrict__ xp =
                reinterpret_cast<const float4*>(x) + (size_t)plane * NHW4;
            float4* __restrict__ sb = reinterpret_cast<float4*>(sbuf[buf]);

            float4 v[3];
            #pragma unroll
            for (int k = 0; k < 3; k++)              // 3*256 = 768
                v[k] = xp[tid + k * 256];
            #pragma unroll
            for (int k = 0; k < 3; k++) {
                float4 r;
                r.x = fmaf(v[k].x, sc, sf);
                r.y = fmaf(v[k].y, sc, sf);
                r.z = fmaf(v[k].z, sc, sf);
                r.w = fmaf(v[k].w, sc, sf);
                sb[tid + k * 256] = r;
            }
            if (tid < 16) {                          // tail 784-768 = 16
                float4 t = xp[768 + tid];
                float4 r;
                r.x = fmaf(t.x, sc, sf);
                r.y = fmaf(t.y, sc, sf);
                r.z = fmaf(t.z, sc, sf);
                r.w = fmaf(t.w, sc, sf);
                sb[768 + tid] = r;
            }
            __syncthreads();

            if (tid == 0) {
                asm volatile("fence.proxy.async.shared::cta;" ::: "memory");
                uint32_t saddr = (uint32_t)__cvta_generic_to_shared(sbuf[buf]);
                asm volatile(
                    "cp.async.bulk.global.shared::cta.bulk_group [%0], [%1], %2;"
                    :: "l"(out + (size_t)plane * NHW), "r"(saddr),
                       "r"((uint32_t)PLANE_BYTES)
                    : "memory");
                asm volatile("cp.async.bulk.commit_group;" ::: "memory");
            }
            buf = (buf + 1 == NBUF) ? 0 : buf + 1;
        }
    }

    // drain all outstanding bulk stores before kernel exit
    if (tid == 0)
        asm volatile("cp.async.bulk.wait_group 0;" ::: "memory");
    __syncthreads();
}

extern "C" void kernel_launch(void* const* d_in, const int* in_sizes, int n_in,
                              void* d_out, int out_size) {
    const float* x       = (const float*)d_in[0];
    // d_in[1] = labels (unused)
    const float* alpha_w = (const float*)d_in[2];
    const float* alpha_b = (const float*)d_in[3];
    const float* g_w     = (const float*)d_in[4];
    const float* g_b     = (const float*)d_in[5];
    const float* g_rm    = (const float*)d_in[6];
    const float* g_rv    = (const float*)d_in[7];
    const float* grp_w   = (const float*)d_in[8];
    const float* grp_b   = (const float*)d_in[9];
    const float* grp_rm  = (const float*)d_in[10];
    const float* grp_rv  = (const float*)d_in[11];
    float* out = (float*)d_out;

    fused_kernel<<<GRID_BLOCKS, TPB>>>(x, out,
                                       alpha_w, alpha_b,
                                       g_w, g_b, g_rm, g_rv,
                                       grp_w, grp_b, grp_rm, grp_rv);
}

// round 14
// speedup vs baseline: 1.2622x; 1.2622x over previous
#include <cuda_runtime.h>
#include <cstdint>

#define NB 32
#define NC 256
#define NHW 3136
#define NHW4 784
#define NG 32
#define EPSV 1e-5f

#define GRID_BLOCKS 740      // 5 * 148, co-resident at 5 blocks/SM
#define TPB 256
#define NSTAGE 2
#define PLANES_PER_STAGE 4096
#define BATCHES_PER_STAGE 16
#define PLANE_BYTES (NHW * 4)   // 12544
#define NBUF 3

__device__ float4 d_coef[NC];          // (gs, gsh, ms, msh) per channel
__device__ float  d_dot[NB];           // alpha dot accumulators (zero-init)

__device__ unsigned int bar_count = 0;
__device__ volatile unsigned int bar_gen = 0;
__device__ unsigned int pool_ctr[NSTAGE];
__device__ unsigned int apply_ctr[NSTAGE];

__device__ __forceinline__ void grid_barrier_reset(int s) {
    __threadfence();          // publish pool-phase writes
    __syncthreads();
    if (threadIdx.x == 0) {
        const unsigned int gen = bar_gen;
        if (atomicAdd(&bar_count, 1u) == GRID_BLOCKS - 1) {
            bar_count    = 0;
            pool_ctr[s]  = 0;                 // fully consumed this phase
            apply_ctr[s] = 0;                 // consumed last replay
            const int ob = (s ^ 1) * BATCHES_PER_STAGE;
            #pragma unroll
            for (int i = 0; i < BATCHES_PER_STAGE; i++) d_dot[ob + i] = 0.0f;
            __threadfence();
            bar_gen = gen + 1;                // release
        } else {
            while (bar_gen == gen) __nanosleep(32);
        }
        __threadfence();                      // acquire
    }
    __syncthreads();
}

__global__ __launch_bounds__(TPB, 5)
void fused_kernel(const float* __restrict__ x, float* __restrict__ out,
                  const float* __restrict__ alpha_w,
                  const float* __restrict__ alpha_b,
                  const float* __restrict__ g_w,
                  const float* __restrict__ g_b,
                  const float* __restrict__ g_rm,
                  const float* __restrict__ g_rv,
                  const float* __restrict__ grp_w,
                  const float* __restrict__ grp_b,
                  const float* __restrict__ grp_rm,
                  const float* __restrict__ grp_rv) {
    __shared__ __align__(128) float sbuf[NBUF][NHW];   // 3 x 12.25KB
    __shared__ unsigned int s_grain;

    const int tid  = threadIdx.x;
    const int lane = tid & 31;

    // block 0 builds the per-channel coefficient table while others pool
    if (blockIdx.x == 0) {
        const int c = tid;
        const float gs  = g_w[c] * rsqrtf(g_rv[c] + EPSV);
        const float gsh = g_b[c] - g_rm[c] * gs;
        float ms = 0.0f, msh = 0.0f;
        #pragma unroll 8
        for (int g = 0; g < NG; g++) {
            const int idx = g * NC + c;
            const float sg = grp_w[idx] * rsqrtf(grp_rv[idx] + EPSV);
            ms  += sg;
            msh += grp_b[idx] - grp_rm[idx] * sg;
        }
        d_coef[c] = make_float4(gs, gsh, ms * (1.0f / (float)NG),
                                         msh * (1.0f / (float)NG));
    }

    int buf = 0;   // TMA buffer cursor persists across stages

    #pragma unroll 1
    for (int stage = 0; stage < NSTAGE; stage++) {

        // ---------- pool phase: warp-steal whole planes, fold alpha-dot ----
        for (;;) {
            unsigned int pz;
            if (lane == 0) pz = atomicAdd(&pool_ctr[stage], 1u);
            pz = __shfl_sync(0xffffffffu, pz, 0);
            if (pz >= PLANES_PER_STAGE) break;
            const int plane = stage * PLANES_PER_STAGE + (int)pz;

            const float4* __restrict__ xp =
                reinterpret_cast<const float4*>(x) + (size_t)plane * NHW4;
            float s = 0.0f;
            float4 v[6];
            #pragma unroll
            for (int b = 0; b < 4; b++) {            // 4*6*32 = 768
                #pragma unroll
                for (int k = 0; k < 6; k++)
                    v[k] = xp[lane + (b * 6 + k) * 32];
                #pragma unroll
                for (int k = 0; k < 6; k++)
                    s += (v[k].x + v[k].y) + (v[k].z + v[k].w);
            }
            if (lane < 16) {                         // tail 16
                float4 t = xp[768 + lane];
                s += (t.x + t.y) + (t.z + t.w);
            }
            #pragma unroll
            for (int o = 16; o > 0; o >>= 1)
                s += __shfl_down_sync(0xffffffffu, s, o);
            if (lane == 0) {
                const float p = s * (1.0f / (float)NHW);
                atomicAdd(&d_dot[plane >> 8], p * alpha_w[plane & 255]);
            }
        }

        grid_barrier_reset(stage);

        // ---------- apply phase: block-steal planes; 3-deep TMA pipeline ---
        for (;;) {
            // thread 0: fetch grain AND drain reused buffer, then one sync
            if (tid == 0) {
                s_grain = atomicAdd(&apply_ctr[stage], 1u);
                asm volatile("cp.async.bulk.wait_group 2;" ::: "memory");
            }
            __syncthreads();
            const unsigned int g = s_grain;
            if (g >= PLANES_PER_STAGE) break;
            const int plane = stage * PLANES_PER_STAGE + (int)g;

            const float4 cf = d_coef[plane & 255];
            const float a   = 1.0f / (1.0f + expf(-(d_dot[plane >> 8] + alpha_b[0])));
            const float na  = 1.0f - a;
            const float sc  = na * cf.x + a * cf.z;
            const float sf  = na * cf.y + a * cf.w;

            const float4* __restrict__ xp =
                reinterpret_cast<const float4*>(x) + (size_t)plane * NHW4;
            float4* __restrict__ sb = reinterpret_cast<float4*>(sbuf[buf]);

            float4 v[3];
            #pragma unroll
            for (int k = 0; k < 3; k++)              // 3*256 = 768
                v[k] = xp[tid + k * 256];
            #pragma unroll
            for (int k = 0; k < 3; k++) {
                float4 r;
                r.x = fmaf(v[k].x, sc, sf);
                r.y = fmaf(v[k].y, sc, sf);
                r.z = fmaf(v[k].z, sc, sf);
                r.w = fmaf(v[k].w, sc, sf);
                sb[tid + k * 256] = r;
            }
            if (tid < 16) {                          // tail 784-768 = 16
                float4 t = xp[768 + tid];
                float4 r;
                r.x = fmaf(t.x, sc, sf);
                r.y = fmaf(t.y, sc, sf);
                r.z = fmaf(t.z, sc, sf);
                r.w = fmaf(t.w, sc, sf);
                sb[768 + tid] = r;
            }
            __syncthreads();

            if (tid == 0) {
                asm volatile("fence.proxy.async.shared::cta;" ::: "memory");
                uint32_t saddr = (uint32_t)__cvta_generic_to_shared(sbuf[buf]);
                asm volatile(
                    "cp.async.bulk.global.shared::cta.bulk_group [%0], [%1], %2;"
                    :: "l"(out + (size_t)plane * NHW), "r"(saddr),
                       "r"((uint32_t)PLANE_BYTES)
                    : "memory");
                asm volatile("cp.async.bulk.commit_group;" ::: "memory");
            }
            buf = (buf + 1 == NBUF) ? 0 : buf + 1;
        }
    }

    // drain all outstanding bulk stores before kernel exit
    if (tid == 0)
        asm volatile("cp.async.bulk.wait_group 0;" ::: "memory");
    __syncthreads();
}

extern "C" void kernel_launch(void* const* d_in, const int* in_sizes, int n_in,
                              void* d_out, int out_size) {
    const float* x       = (const float*)d_in[0];
    // d_in[1] = labels (unused)
    const float* alpha_w = (const float*)d_in[2];
    const float* alpha_b = (const float*)d_in[3];
    const float* g_w     = (const float*)d_in[4];
    const float* g_b     = (const float*)d_in[5];
    const float* g_rm    = (const float*)d_in[6];
    const float* g_rv    = (const float*)d_in[7];
    const float* grp_w   = (const float*)d_in[8];
    const float* grp_b   = (const float*)d_in[9];
    const float* grp_rm  = (const float*)d_in[10];
    const float* grp_rv  = (const float*)d_in[11];
    float* out = (float*)d_out;

    fused_kernel<<<GRID_BLOCKS, TPB>>>(x, out,
                                       alpha_w, alpha_b,
                                       g_w, g_b, g_rm, g_rv,
                                       grp_w, grp_b, grp_rm, grp_rv);
}